// round 12
// baseline (speedup 1.0000x reference)
#include <cuda_runtime.h>

#define NRAD  16
#define NL    2
#define NOUT  144            // 16*(1 + 2*4)
#define L35   35
#define KG    9              // 9 chunks of 4 k-values (36 padded)
#define HALFT 144            // threads per atom: 16 j x 9 kg
#define BLOCK 288            // 2 atoms per block -> 9 full warps
#define MAXE   100000
#define MAXNAT 4096
#define PGRID  592           // 148 SMs x 4 blocks/SM -> exactly one wave

__device__ int    g_segstart[MAXNAT + 1];
__device__ float4 g_gT[KG * MAXE];      // [kg][e]: 4 monomials, k=35 padded to 0

typedef unsigned long long ull;

__device__ __forceinline__ ull pack2(float x, float y) {
    ull r; asm("mov.b64 %0, {%1, %2};" : "=l"(r) : "f"(x), "f"(y)); return r;
}
__device__ __forceinline__ ull dup2(float x) {
    ull r; asm("mov.b64 %0, {%1, %1};" : "=l"(r) : "f"(x)); return r;
}
__device__ __forceinline__ void unpack2(ull p, float& x, float& y) {
    asm("mov.b64 {%0, %1}, %2;" : "=f"(x), "=f"(y) : "l"(p));
}
__device__ __forceinline__ void fma2(ull& d, ull a, ull b) {
    asm("fma.rn.f32x2 %0, %1, %2, %0;" : "+l"(d) : "l"(a), "l"(b));
}

__constant__ int c_S[L35] = {0, 1,1,1, 2,2,2,2,2,2,
                             3,3,3,3,3,3,3,3,3,3,
                             4,4,4,4,4,4,4,4,4,4,4,4,4,4,4};

// Fused prepass: angular monomials -> g_gT, plus segment starts.
__global__ __launch_bounds__(256)
void prep_kernel(const float* __restrict__ rij, const int* __restrict__ fidx,
                 int E, int nat)
{
    constexpr int LXc[L35] = {0, 0,0,1, 0,0,0,1,1,2,
                              0,0,0,0,1,1,1,2,2,3,
                              0,0,0,0,0,1,1,1,1,2,2,2,3,3,4};
    constexpr int LYc[L35] = {0, 0,1,0, 0,1,2,0,1,0,
                              0,1,2,3,0,1,2,0,1,0,
                              0,1,2,3,4,0,1,2,3,0,1,2,0,1,0};
    constexpr int LZc[L35] = {0, 1,0,0, 2,1,0,1,0,0,
                              3,2,1,0,2,1,0,1,0,0,
                              4,3,2,1,0,3,2,1,0,2,1,0,1,0,0};
    constexpr float FNc[L35] = {1.f, 1.f,1.f,1.f,
                                1.f,2.f,1.f,2.f,2.f,1.f,
                                1.f,3.f,3.f,1.f,3.f,6.f,3.f,3.f,3.f,1.f,
                                1.f,4.f,6.f,4.f,1.f,4.f,12.f,12.f,4.f,
                                6.f,12.f,6.f,4.f,4.f,1.f};
    int e = blockIdx.x * blockDim.x + threadIdx.x;
    if (e >= E) return;

    // segment starts (fidx sorted ascending)
    {
        int cur  = fidx[e];
        int prev = (e == 0) ? -1 : fidx[e - 1];
        for (int a = prev + 1; a <= cur; a++) g_segstart[a] = e;
        if (e == E - 1)
            for (int a = cur + 1; a <= nat; a++) g_segstart[a] = E;
    }

    float x = rij[e*3+0], y = rij[e*3+1], z = rij[e*3+2];
    float px[5], py[5], pz[5];
    px[0]=1.f; px[1]=x; px[2]=x*x; px[3]=px[2]*x; px[4]=px[2]*px[2];
    py[0]=1.f; py[1]=y; py[2]=y*y; py[3]=py[2]*y; py[4]=py[2]*py[2];
    pz[0]=1.f; pz[1]=z; pz[2]=z*z; pz[3]=pz[2]*z; pz[4]=pz[2]*pz[2];
    float g[36];
    #pragma unroll
    for (int k = 0; k < L35; k++)
        g[k] = FNc[k] * px[LXc[k]] * py[LYc[k]] * pz[LZc[k]];
    g[35] = 0.f;
    #pragma unroll
    for (int kg = 0; kg < KG; kg++)
        g_gT[kg * MAXE + e] = make_float4(g[kg*4+0], g[kg*4+1], g[kg*4+2], g[kg*4+3]);
}

__global__ __launch_bounds__(BLOCK, 4)
void mbp_main(const float* __restrict__ radial,   // [E,16,5]
              const float* __restrict__ lamw,     // [NL]
              float* __restrict__ out,            // [nat, NOUT]
              int nat)
{
    __shared__ float s_lam[NL][36];
    __shared__ float s_part[2][KG][NRAD][8];

    const int tid  = threadIdx.x;
    const int half = (tid >= HALFT) ? 1 : 0;
    const int t    = tid - half * HALFT;
    const int j    = t & 15;        // 0..15 radial index
    const int kg   = t >> 4;        // 0..8  angular chunk

    if (tid < NL * 36) {
        int l = (tid >= 36) ? 1 : 0;
        int k = tid - l * 36;
        float p = 0.f;
        if (k < L35) {
            float b = lamw[l];
            int   s = c_S[k];
            p = 1.f;                       // exact integer power (b may be < 0)
            for (int i = 0; i < s; i++) p *= b;
        }
        s_lam[l][k] = p;
    }
    __syncthreads();

    const int npair = (nat + 1) >> 1;

    for (int pair = blockIdx.x; pair < npair; pair += PGRID) {
        const int a = pair * 2 + half;
        const int start = (a < nat) ? g_segstart[a]     : 0;
        const int end   = (a < nat) ? g_segstart[a + 1] : 0;

        ull acc0[4] = {0,0,0,0};        // (k0,k0+1) per channel
        ull acc1[4] = {0,0,0,0};        // (k0+2,k0+3) per channel
        float accR = 0.f;               // two-body channel (kg==0 only)

        const float*  rp = radial + (size_t)start * 80 + j * 5;
        const float4* gp = g_gT + (size_t)kg * MAXE + start;

        #pragma unroll 8
        for (int e = start; e < end; e++) {
            float4 g4 = *gp++;
            float r0 = rp[0], r1 = rp[1], r2 = rp[2], r3 = rp[3];
            if (kg == 0) accR += rp[4];
            rp += 80;
            ull gA = pack2(g4.x, g4.y);
            ull gB = pack2(g4.z, g4.w);
            ull d0 = dup2(r0), d1 = dup2(r1), d2 = dup2(r2), d3 = dup2(r3);
            fma2(acc0[0], gA, d0);  fma2(acc1[0], gB, d0);
            fma2(acc0[1], gA, d1);  fma2(acc1[1], gB, d1);
            fma2(acc0[2], gA, d2);  fma2(acc1[2], gB, d2);
            fma2(acc0[3], gA, d3);  fma2(acc1[3], gB, d3);
        }

        // per-thread partial lambda contraction over this thread's 4 k-values
        {
            float lv0[4], lv1[4];
            #pragma unroll
            for (int q = 0; q < 4; q++) {
                lv0[q] = s_lam[0][kg*4 + q];
                lv1[q] = s_lam[1][kg*4 + q];
            }
            #pragma unroll
            for (int c = 0; c < 4; c++) {
                float u, v, w, tt;
                unpack2(acc0[c], u, v);
                unpack2(acc1[c], w, tt);
                float s0 = u*u, s1 = v*v, s2 = w*w, s3 = tt*tt;
                float p0 = fmaf(s0, lv0[0], fmaf(s1, lv0[1], fmaf(s2, lv0[2], s3*lv0[3])));
                float p1 = fmaf(s0, lv1[0], fmaf(s1, lv1[1], fmaf(s2, lv1[2], s3*lv1[3])));
                s_part[half][kg][j][c*2 + 0] = p0;
                s_part[half][kg][j][c*2 + 1] = p1;
            }
        }
        if (kg == 0 && a < nat) out[(size_t)a * NOUT + j] = accR;
        __syncthreads();

        // reduce over kg groups: 256 outputs = 2 atoms x (j2, c, l)
        if (tid < 256) {
            int h2  = tid >> 7;          // atom half
            int low = tid & 127;
            int co  = low & 7;           // c*2 + l
            int j2  = low >> 3;          // 0..15
            int ao  = pair * 2 + h2;
            if (ao < nat) {
                float sum = 0.f;
                #pragma unroll
                for (int k = 0; k < KG; k++) sum += s_part[h2][k][j2][co];
                int c = co >> 1, l = co & 1;
                float scale = __int_as_float(0x3F800000 - (c << 23));   // 2^-c
                out[(size_t)ao * NOUT + NRAD + c*(NRAD*NL) + j2*NL + l] = sum * scale;
            }
        }
        __syncthreads();                 // WAR: s_part reused next pair
    }
}

extern "C" void kernel_launch(void* const* d_in, const int* in_sizes, int n_in,
                              void* d_out, int out_size)
{
    const float* rij    = (const float*)d_in[0];   // [E,3]
    const float* radial = (const float*)d_in[1];   // [E,16,5]
    const float* lamw   = (const float*)d_in[2];   // [2]
    const int*   fidx   = (const int*)  d_in[4];   // [E] sorted

    const int E   = in_sizes[0] / 3;
    const int nat = out_size / NOUT;

    const int npair = (nat + 1) / 2;
    const int grid  = npair < PGRID ? npair : PGRID;

    prep_kernel<<<(E + 255) / 256, 256>>>(rij, fidx, E, nat);
    mbp_main  <<<grid, BLOCK>>>(radial, lamw, (float*)d_out, nat);
}

// round 13
// speedup vs baseline: 1.0019x; 1.0019x over previous
#include <cuda_runtime.h>

#define NRAD  16
#define NL    2
#define NOUT  144            // 16*(1 + 2*4)
#define L35   35
#define KG    9              // 9 chunks of 4 k-values (36 padded)
#define HALFT 144            // threads per atom: 16 j x 9 kg
#define BLOCK 288            // 2 atoms per block -> 9 full warps
#define MAXE   100000
#define MAXNAT 4096

__device__ int    g_segstart[MAXNAT + 1];
__device__ float4 g_gT[KG * MAXE];      // [kg][e]: 4 monomials, k=35 padded to 0

typedef unsigned long long ull;

__device__ __forceinline__ ull pack2(float x, float y) {
    ull r; asm("mov.b64 %0, {%1, %2};" : "=l"(r) : "f"(x), "f"(y)); return r;
}
__device__ __forceinline__ ull dup2(float x) {
    ull r; asm("mov.b64 %0, {%1, %1};" : "=l"(r) : "f"(x)); return r;
}
__device__ __forceinline__ void unpack2(ull p, float& x, float& y) {
    asm("mov.b64 {%0, %1}, %2;" : "=f"(x), "=f"(y) : "l"(p));
}
__device__ __forceinline__ void fma2(ull& d, ull a, ull b) {
    asm("fma.rn.f32x2 %0, %1, %2, %0;" : "+l"(d) : "l"(a), "l"(b));
}

__constant__ int c_S[L35] = {0, 1,1,1, 2,2,2,2,2,2,
                             3,3,3,3,3,3,3,3,3,3,
                             4,4,4,4,4,4,4,4,4,4,4,4,4,4,4};

// Fused prepass: angular monomials -> g_gT, plus segment starts.
__global__ __launch_bounds__(256)
void prep_kernel(const float* __restrict__ rij, const int* __restrict__ fidx,
                 int E, int nat)
{
    constexpr int LXc[L35] = {0, 0,0,1, 0,0,0,1,1,2,
                              0,0,0,0,1,1,1,2,2,3,
                              0,0,0,0,0,1,1,1,1,2,2,2,3,3,4};
    constexpr int LYc[L35] = {0, 0,1,0, 0,1,2,0,1,0,
                              0,1,2,3,0,1,2,0,1,0,
                              0,1,2,3,4,0,1,2,3,0,1,2,0,1,0};
    constexpr int LZc[L35] = {0, 1,0,0, 2,1,0,1,0,0,
                              3,2,1,0,2,1,0,1,0,0,
                              4,3,2,1,0,3,2,1,0,2,1,0,1,0,0};
    constexpr float FNc[L35] = {1.f, 1.f,1.f,1.f,
                                1.f,2.f,1.f,2.f,2.f,1.f,
                                1.f,3.f,3.f,1.f,3.f,6.f,3.f,3.f,3.f,1.f,
                                1.f,4.f,6.f,4.f,1.f,4.f,12.f,12.f,4.f,
                                6.f,12.f,6.f,4.f,4.f,1.f};
    int e = blockIdx.x * blockDim.x + threadIdx.x;
    if (e >= E) return;

    // segment starts (fidx sorted ascending)
    {
        int cur  = fidx[e];
        int prev = (e == 0) ? -1 : fidx[e - 1];
        for (int a = prev + 1; a <= cur; a++) g_segstart[a] = e;
        if (e == E - 1)
            for (int a = cur + 1; a <= nat; a++) g_segstart[a] = E;
    }

    float x = rij[e*3+0], y = rij[e*3+1], z = rij[e*3+2];
    float px[5], py[5], pz[5];
    px[0]=1.f; px[1]=x; px[2]=x*x; px[3]=px[2]*x; px[4]=px[2]*px[2];
    py[0]=1.f; py[1]=y; py[2]=y*y; py[3]=py[2]*y; py[4]=py[2]*py[2];
    pz[0]=1.f; pz[1]=z; pz[2]=z*z; pz[3]=pz[2]*z; pz[4]=pz[2]*pz[2];
    float g[36];
    #pragma unroll
    for (int k = 0; k < L35; k++)
        g[k] = FNc[k] * px[LXc[k]] * py[LYc[k]] * pz[LZc[k]];
    g[35] = 0.f;
    #pragma unroll
    for (int kg = 0; kg < KG; kg++)
        g_gT[kg * MAXE + e] = make_float4(g[kg*4+0], g[kg*4+1], g[kg*4+2], g[kg*4+3]);
}

__global__ __launch_bounds__(BLOCK, 5)
void mbp_main(const float* __restrict__ radial,   // [E,16,5]
              const float* __restrict__ lamw,     // [NL]
              float* __restrict__ out,            // [nat, NOUT]
              int nat)
{
    __shared__ float s_lam[NL][36];
    __shared__ float s_part[2][KG][NRAD][8];

    const int tid  = threadIdx.x;
    const int half = (tid >= HALFT) ? 1 : 0;
    const int t    = tid - half * HALFT;
    const int j    = t & 15;        // 0..15 radial index
    const int kg   = t >> 4;        // 0..8  angular chunk
    const int a    = blockIdx.x * 2 + half;

    if (tid < NL * 36) {
        int l = (tid >= 36) ? 1 : 0;
        int k = tid - l * 36;
        float p = 0.f;
        if (k < L35) {
            float b = lamw[l];
            int   s = c_S[k];
            p = 1.f;                       // exact integer power (b may be < 0)
            for (int i = 0; i < s; i++) p *= b;
        }
        s_lam[l][k] = p;
    }
    const int start = (a < nat) ? g_segstart[a]     : 0;
    const int end   = (a < nat) ? g_segstart[a + 1] : 0;
    __syncthreads();

    ull acc0[4] = {0,0,0,0};        // (k0,k0+1) per channel
    ull acc1[4] = {0,0,0,0};        // (k0+2,k0+3) per channel
    float accR = 0.f;               // two-body channel (kg==0 only)

    const float*  rp = radial + (size_t)start * 80 + j * 5;
    const float4* gp = g_gT + (size_t)kg * MAXE + start;

    #pragma unroll 8
    for (int e = start; e < end; e++) {
        float4 g4 = *gp++;
        float r0 = rp[0], r1 = rp[1], r2 = rp[2], r3 = rp[3];
        if (kg == 0) accR += rp[4];
        rp += 80;
        ull gA = pack2(g4.x, g4.y);
        ull gB = pack2(g4.z, g4.w);
        ull d0 = dup2(r0), d1 = dup2(r1), d2 = dup2(r2), d3 = dup2(r3);
        fma2(acc0[0], gA, d0);  fma2(acc1[0], gB, d0);
        fma2(acc0[1], gA, d1);  fma2(acc1[1], gB, d1);
        fma2(acc0[2], gA, d2);  fma2(acc1[2], gB, d2);
        fma2(acc0[3], gA, d3);  fma2(acc1[3], gB, d3);
    }

    // per-thread partial lambda contraction over this thread's 4 k-values
    {
        float lv0[4], lv1[4];
        #pragma unroll
        for (int q = 0; q < 4; q++) {
            lv0[q] = s_lam[0][kg*4 + q];
            lv1[q] = s_lam[1][kg*4 + q];
        }
        #pragma unroll
        for (int c = 0; c < 4; c++) {
            float u, v, w, tt;
            unpack2(acc0[c], u, v);
            unpack2(acc1[c], w, tt);
            float s0 = u*u, s1 = v*v, s2 = w*w, s3 = tt*tt;
            float p0 = fmaf(s0, lv0[0], fmaf(s1, lv0[1], fmaf(s2, lv0[2], s3*lv0[3])));
            float p1 = fmaf(s0, lv1[0], fmaf(s1, lv1[1], fmaf(s2, lv1[2], s3*lv1[3])));
            s_part[half][kg][j][c*2 + 0] = p0;
            s_part[half][kg][j][c*2 + 1] = p1;
        }
    }
    if (kg == 0 && a < nat) out[(size_t)a * NOUT + j] = accR;
    __syncthreads();

    // reduce over kg groups: 256 outputs = 2 atoms x (j2, c, l)
    if (tid < 256) {
        int h2  = tid >> 7;          // atom half
        int low = tid & 127;
        int co  = low & 7;           // c*2 + l
        int j2  = low >> 3;          // 0..15
        int ao  = blockIdx.x * 2 + h2;
        if (ao < nat) {
            float sum = 0.f;
            #pragma unroll
            for (int k = 0; k < KG; k++) sum += s_part[h2][k][j2][co];
            int c = co >> 1, l = co & 1;
            float scale = __int_as_float(0x3F800000 - (c << 23));   // 2^-c
            out[(size_t)ao * NOUT + NRAD + c*(NRAD*NL) + j2*NL + l] = sum * scale;
        }
    }
}

extern "C" void kernel_launch(void* const* d_in, const int* in_sizes, int n_in,
                              void* d_out, int out_size)
{
    const float* rij    = (const float*)d_in[0];   // [E,3]
    const float* radial = (const float*)d_in[1];   // [E,16,5]
    const float* lamw   = (const float*)d_in[2];   // [2]
    const int*   fidx   = (const int*)  d_in[4];   // [E] sorted

    const int E   = in_sizes[0] / 3;
    const int nat = out_size / NOUT;

    prep_kernel<<<(E + 255) / 256, 256>>>(rij, fidx, E, nat);
    mbp_main  <<<(nat + 1) / 2, BLOCK>>>(radial, lamw, (float*)d_out, nat);
}